// round 5
// baseline (speedup 1.0000x reference)
#include <cuda_runtime.h>

// ---------------------------------------------------------------------------
// AttentionSeq2SeqModel: B=512, S=14, H=128, IN=1, target_len=8
// outputs [B,8,1] followed by total_attn [B,14,1] in d_out (fp32).
//
// Strategy: 128 CTAs x 512 threads, 4 batch rows per CTA (rows independent ->
// no inter-CTA sync). Thread n computes gate column n for its 4 rows.
// Whh_d: k<100 cached transposed in smem (conflict-free LDS.128),
// k in [100,128) streamed coalesced from L2. Packed fma.rn.f32x2 mainloop.
// ---------------------------------------------------------------------------

#define B_   512
#define S_   14
#define H_   128
#define NG   512      // 4*H
#define R_   4        // rows per CTA
#define TPB  512
#define NCTA (B_ / R_)
#define KC   100      // k-rows of Whh_d cached in smem (div by 4; 100%32==4 -> conflict-free)
#define TLEN 8

typedef unsigned long long u64;

// persistent scratch (allowed: __device__ globals, no allocation)
__device__ float g_enc[B_ * S_ * H_];      // encoder hidden states
__device__ float g_encProj[B_ * S_ * H_];  // enc_out @ We (computed once)

union F2U { float2 f; u64 u; };

__device__ __forceinline__ void fma2(u64 &acc, u64 a, u64 b) {
    asm("fma.rn.f32x2 %0, %1, %2, %0;" : "+l"(acc) : "l"(a), "l"(b));
}

__device__ __forceinline__ float sigm(float x) {
    return __fdividef(1.0f, 1.0f + __expf(-x));
}
__device__ __forceinline__ float tanh_(float x) {
    return __fdividef(2.0f, 1.0f + __expf(-2.0f * x)) - 1.0f;
}

// g[m][n] = init_m + sum_k hs[m][k] * W[k][n]; W split smem(k<KCACHE)/global.
template <int KCACHE>
__device__ __forceinline__ void gate_mm(
    const float* __restrict__ hs,
    const float* __restrict__ Wsm,
    const float* __restrict__ Wg,
    int n,
    float i0, float i1, float i2, float i3,
    float* __restrict__ gates)
{
    F2U t;
    u64 a0, a1, a2, a3;
    t.f = make_float2(i0, 0.f); a0 = t.u;
    t.f = make_float2(i1, 0.f); a1 = t.u;
    t.f = make_float2(i2, 0.f); a2 = t.u;
    t.f = make_float2(i3, 0.f); a3 = t.u;

    const ulonglong2* h0p = reinterpret_cast<const ulonglong2*>(hs);
    const ulonglong2* h1p = reinterpret_cast<const ulonglong2*>(hs + H_);
    const ulonglong2* h2p = reinterpret_cast<const ulonglong2*>(hs + 2 * H_);
    const ulonglong2* h3p = reinterpret_cast<const ulonglong2*>(hs + 3 * H_);

    if (KCACHE > 0) {
        const ulonglong2* wp = reinterpret_cast<const ulonglong2*>(Wsm + n * KCACHE);
#pragma unroll
        for (int i = 0; i < KCACHE / 4; i++) {
            ulonglong2 w  = wp[i];
            ulonglong2 h0 = h0p[i], h1 = h1p[i], h2 = h2p[i], h3 = h3p[i];
            fma2(a0, h0.x, w.x); fma2(a0, h0.y, w.y);
            fma2(a1, h1.x, w.x); fma2(a1, h1.y, w.y);
            fma2(a2, h2.x, w.x); fma2(a2, h2.y, w.y);
            fma2(a3, h3.x, w.x); fma2(a3, h3.y, w.y);
        }
    }
#pragma unroll
    for (int i = KCACHE / 4; i < H_ / 4; i++) {
        const int k = i * 4;
        float w0 = __ldg(Wg + (size_t)(k + 0) * NG + n);
        float w1 = __ldg(Wg + (size_t)(k + 1) * NG + n);
        float w2 = __ldg(Wg + (size_t)(k + 2) * NG + n);
        float w3 = __ldg(Wg + (size_t)(k + 3) * NG + n);
        F2U wa, wb;
        wa.f = make_float2(w0, w1);
        wb.f = make_float2(w2, w3);
        ulonglong2 h0 = h0p[i], h1 = h1p[i], h2 = h2p[i], h3 = h3p[i];
        fma2(a0, h0.x, wa.u); fma2(a0, h0.y, wb.u);
        fma2(a1, h1.x, wa.u); fma2(a1, h1.y, wb.u);
        fma2(a2, h2.x, wa.u); fma2(a2, h2.y, wb.u);
        fma2(a3, h3.x, wa.u); fma2(a3, h3.y, wb.u);
    }
    t.u = a0; gates[n]          = t.f.x + t.f.y;
    t.u = a1; gates[NG + n]     = t.f.x + t.f.y;
    t.u = a2; gates[2 * NG + n] = t.f.x + t.f.y;
    t.u = a3; gates[3 * NG + n] = t.f.x + t.f.y;
}

__device__ __forceinline__ float warpsum(float v) {
    v += __shfl_xor_sync(0xffffffffu, v, 16);
    v += __shfl_xor_sync(0xffffffffu, v, 8);
    v += __shfl_xor_sync(0xffffffffu, v, 4);
    v += __shfl_xor_sync(0xffffffffu, v, 2);
    v += __shfl_xor_sync(0xffffffffu, v, 1);
    return v;
}

__global__ __launch_bounds__(TPB, 1)
void seq2seq_kernel(
    const float* __restrict__ inputs,
    const float* __restrict__ Wih_e, const float* __restrict__ Whh_e, const float* __restrict__ b_e,
    const float* __restrict__ Wih_d, const float* __restrict__ Whh_d, const float* __restrict__ b_d,
    const float* __restrict__ We,    const float* __restrict__ Wd,
    const float* __restrict__ Wv,    const float* __restrict__ Wf,    const float* __restrict__ bf,
    float* __restrict__ out, int write_attn)
{
    extern __shared__ float smf[];
    float* Wsm     = smf;                     // NG*KC           = 51200
    float* hs      = Wsm + NG * KC;           // R_*H_           = 512
    float* gates   = hs + R_ * H_;            // R_*NG           = 2048
    float* xs      = gates + R_ * NG;         // R_              = 4
    float* xenc    = xs + R_;                 // R_*S_           = 56
    float* attn    = xenc + R_ * S_;          // R_*S_           = 56
    float* attnAcc = attn + R_ * S_;          // R_*S_           = 56
    float* red     = attnAcc + R_ * S_;       // R_*S_*4         = 224
    float* ctx     = red + R_ * S_ * 4;       // R_*H_           = 512 (hWd / context buffer)

    const int tid  = threadIdx.x;
    const int n    = tid;
    const int m    = tid >> 7;      // row-in-CTA for (m,j) role
    const int j    = tid & 127;
    const int lane = tid & 31;
    const int wig  = (tid >> 5) & 3;
    const int cta  = blockIdx.x;
    const int row  = cta * R_ + m;

    // Stage Whh_d transposed into smem: Wsm[n][k], k in [0,KC). Coalesced reads.
    for (int idx = tid; idx < NG * KC; idx += TPB) {
        int k  = idx / NG;
        int nn = idx % NG;
        Wsm[nn * KC + k] = Whh_d[(size_t)k * NG + nn];
    }
    hs[tid] = 0.f;
    if (tid < R_ * S_) {
        attnAcc[tid] = 0.f;
        int mm = tid / S_, tt = tid % S_;
        xenc[tid] = inputs[(cta * R_ + mm) * S_ + tt];
    }
    if (tid < R_) xs[tid] = inputs[(cta * R_ + tid) * S_ + (S_ - 1)];
    float c_reg = 0.f;

    const float wihe_n = Wih_e[n], be_n = b_e[n];
    const float wihd_n = Wih_d[n], bd_n = b_d[n];
    const float wv_j = Wv[j];
    const float wf_j = Wf[j];
    const float bf0  = bf[0];
    __syncthreads();

    // ---------------- Encoder: 14 steps ----------------
    for (int t = 0; t < S_; t++) {
        gate_mm<0>(hs, Wsm, Whh_e, n,
                   be_n + xenc[0 * S_ + t] * wihe_n,
                   be_n + xenc[1 * S_ + t] * wihe_n,
                   be_n + xenc[2 * S_ + t] * wihe_n,
                   be_n + xenc[3 * S_ + t] * wihe_n, gates);
        __syncthreads();
        {
            float gi = gates[m * NG + j];
            float gf = gates[m * NG + H_ + j];
            float gg = gates[m * NG + 2 * H_ + j];
            float go = gates[m * NG + 3 * H_ + j];
            float c  = sigm(gf) * c_reg + sigm(gi) * tanh_(gg);
            float h  = sigm(go) * tanh_(c);
            c_reg = c;
            hs[m * H_ + j] = h;
            g_enc[(size_t)row * S_ * H_ + t * H_ + j] = h;
        }
        __syncthreads();
    }

    // encProj[t][j] = sum_k enc[t][k] * We[k][j]  (computed ONCE, reused 8x)
    {
        float acc[S_];
#pragma unroll
        for (int t = 0; t < S_; t++) acc[t] = 0.f;
        const float* eb = g_enc + (size_t)row * S_ * H_;
#pragma unroll 4
        for (int k = 0; k < H_; k++) {
            float we = __ldg(We + k * H_ + j);
#pragma unroll
            for (int t = 0; t < S_; t++) acc[t] += __ldg(eb + t * H_ + k) * we;
        }
        float* pb = g_encProj + (size_t)row * S_ * H_;
#pragma unroll
        for (int t = 0; t < S_; t++) pb[t * H_ + j] = acc[t];
    }
    __syncthreads();

    // ---------------- Decoder: 8 steps ----------------
    for (int s = 0; s < TLEN; s++) {
        // hWd[m][j] = sum_k h[m][k] * Wd[k][j]
        {
            float acc = 0.f;
#pragma unroll 8
            for (int k = 0; k < H_; k++)
                acc += hs[m * H_ + k] * __ldg(Wd + k * H_ + j);
            ctx[m * H_ + j] = acc;
        }
        __syncthreads();
        // scores[t] = sum_j tanh(encProj[t][j] + hWd[j]) * Wv[j]
        {
            float hwd = ctx[m * H_ + j];
            const float* ep = g_encProj + (size_t)row * S_ * H_;
#pragma unroll
            for (int t = 0; t < S_; t++) {
                float v = tanh_(ep[t * H_ + j] + hwd) * wv_j;
                v = warpsum(v);
                if (lane == 0) red[(m * S_ + t) * 4 + wig] = v;
            }
        }
        __syncthreads();
        if (j < S_) {
            int b4 = (m * S_ + j) * 4;
            attn[m * S_ + j] = red[b4] + red[b4 + 1] + red[b4 + 2] + red[b4 + 3];
        }
        __syncthreads();
        if (j == 0) {  // softmax over S per row + accumulate total_attn
            float mx = attn[m * S_];
#pragma unroll
            for (int t = 1; t < S_; t++) mx = fmaxf(mx, attn[m * S_ + t]);
            float ssum = 0.f;
            float ex[S_];
#pragma unroll
            for (int t = 0; t < S_; t++) { ex[t] = __expf(attn[m * S_ + t] - mx); ssum += ex[t]; }
            float inv = __fdividef(1.f, ssum);
#pragma unroll
            for (int t = 0; t < S_; t++) {
                float a_ = ex[t] * inv;
                attn[m * S_ + t] = a_;
                attnAcc[m * S_ + t] += a_;
            }
        }
        __syncthreads();
        // context[m][j] = sum_t attn[t] * enc[t][j]
        {
            const float* eb = g_enc + (size_t)row * S_ * H_;
            float acc = 0.f;
#pragma unroll
            for (int t = 0; t < S_; t++) acc += attn[m * S_ + t] * __ldg(eb + t * H_ + j);
            ctx[m * H_ + j] = acc;
        }
        __syncthreads();

        // inner decoder LSTM over 129 scalar inputs: context[0..127], then x
        for (int js = 0; js < H_ + 1; js++) {
            float x0, x1, x2, x3;
            if (js < H_) {
                x0 = ctx[js]; x1 = ctx[H_ + js]; x2 = ctx[2 * H_ + js]; x3 = ctx[3 * H_ + js];
            } else {
                x0 = xs[0]; x1 = xs[1]; x2 = xs[2]; x3 = xs[3];
            }
            gate_mm<KC>(hs, Wsm, Whh_d, n,
                        bd_n + x0 * wihd_n, bd_n + x1 * wihd_n,
                        bd_n + x2 * wihd_n, bd_n + x3 * wihd_n, gates);
            __syncthreads();
            {
                float gi = gates[m * NG + j];
                float gf = gates[m * NG + H_ + j];
                float gg = gates[m * NG + 2 * H_ + j];
                float go = gates[m * NG + 3 * H_ + j];
                float c  = sigm(gf) * c_reg + sigm(gi) * tanh_(gg);
                float h  = sigm(go) * tanh_(c);
                c_reg = c;
                hs[m * H_ + j] = h;
            }
            __syncthreads();
        }

        // out = h @ Wf + bf ; feed back as next x
        {
            float v = hs[m * H_ + j] * wf_j;
            v = warpsum(v);
            if (lane == 0) red[m * 4 + wig] = v;
        }
        __syncthreads();
        if (j == 0) {
            float o = red[m * 4] + red[m * 4 + 1] + red[m * 4 + 2] + red[m * 4 + 3] + bf0;
            out[row * TLEN + s] = o;
            xs[m] = o;
        }
        __syncthreads();
    }

    if (write_attn && j < S_)
        out[B_ * TLEN + row * S_ + j] = attnAcc[m * S_ + j];
}

extern "C" void kernel_launch(void* const* d_in, const int* in_sizes, int n_in,
                              void* d_out, int out_size) {
    // metadata order: inputs, [target_len], Wih_e, Whh_e, b_e, Wih_d, Whh_d, b_d,
    //                 We, Wd, Wv, Wf, bf
    const float* inputs = (const float*)d_in[0];
    const int off = (n_in >= 13 && in_sizes[1] == 1) ? 2 : 1;
    const float* Wih_e = (const float*)d_in[off + 0];
    const float* Whh_e = (const float*)d_in[off + 1];
    const float* b_e   = (const float*)d_in[off + 2];
    const float* Wih_d = (const float*)d_in[off + 3];
    const float* Whh_d = (const float*)d_in[off + 4];
    const float* b_d   = (const float*)d_in[off + 5];
    const float* We    = (const float*)d_in[off + 6];
    const float* Wd    = (const float*)d_in[off + 7];
    const float* Wv    = (const float*)d_in[off + 8];
    const float* Wf    = (const float*)d_in[off + 9];
    const float* bf    = (const float*)d_in[off + 10];

    const int smem_floats = NG * KC + R_ * H_ + R_ * NG + R_ + 3 * R_ * S_ + R_ * S_ * 4 + R_ * H_;
    const int smem_bytes  = smem_floats * (int)sizeof(float);  // 218672

    cudaFuncSetAttribute(seq2seq_kernel,
                         cudaFuncAttributeMaxDynamicSharedMemorySize, smem_bytes);

    const int write_attn = (out_size >= B_ * TLEN + B_ * S_) ? 1 : 0;

    seq2seq_kernel<<<NCTA, TPB, smem_bytes>>>(
        inputs, Wih_e, Whh_e, b_e, Wih_d, Whh_d, b_d,
        We, Wd, Wv, Wf, bf, (float*)d_out, write_attn);
}

// round 6
// speedup vs baseline: 1.3092x; 1.3092x over previous
#include <cuda_runtime.h>

// ---------------------------------------------------------------------------
// AttentionSeq2SeqModel: B=512, S=14, H=128, IN=1, target_len=8
// out = [B,8,1] outputs followed by [B,14,1] total_attn (fp32).
//
// R6: 128 CTAs x 256 threads (8 warps), 4 batch rows/CTA, 2 gate columns per
// thread (n and n+256). Cuts smem-crossbar wavefronts/step ~4100 -> ~3200
// (the R5 binding resource per ncu: L1 76%). Column remap: thread j<128 owns
// gates i_j,g_j in registers; thread j+128 owns f_j,o_j and stages them via
// smem. Whh (enc then dec) staged transposed in smem for k<100 (conflict-free
// stride-100 LDS.128); k in [100,128) prefetched from L2 into registers
// before the smem mainloop. Packed fma.rn.f32x2 throughout.
// ---------------------------------------------------------------------------

#define B_   512
#define S_   14
#define H_   128
#define NG   512      // 4*H
#define R_   4        // rows per CTA
#define TPB  256
#define NCTA 128
#define KC   100      // k-rows cached in smem (stride 100: conflict-free LDS.128)
#define KT   (H_ - KC) // 28, streamed from L2
#define TLEN 8

typedef unsigned long long u64;

// persistent scratch (__device__ globals: allocation-free)
__device__ float g_enc[B_ * S_ * H_];      // encoder hidden states
__device__ float g_encProj[B_ * S_ * H_];  // enc_out @ We (computed once, reused 8x)

union F2U { float2 f; u64 u; };

__device__ __forceinline__ void fma2(u64 &acc, u64 a, u64 b) {
    asm("fma.rn.f32x2 %0, %1, %2, %0;" : "+l"(acc) : "l"(a), "l"(b));
}
__device__ __forceinline__ float sigm(float x) {
    return __fdividef(1.0f, 1.0f + __expf(-x));
}
__device__ __forceinline__ float tanh_(float x) {
    return __fdividef(2.0f, 1.0f + __expf(-2.0f * x)) - 1.0f;
}
__device__ __forceinline__ float warpsum(float v) {
    v += __shfl_xor_sync(0xffffffffu, v, 16);
    v += __shfl_xor_sync(0xffffffffu, v, 8);
    v += __shfl_xor_sync(0xffffffffu, v, 4);
    v += __shfl_xor_sync(0xffffffffu, v, 2);
    v += __shfl_xor_sync(0xffffffffu, v, 1);
    return v;
}

// Stage W^T into smem: Wsm[n][k] = Wsrc[k][n], k < KC. Coalesced global reads.
__device__ __forceinline__ void stage_w(float* __restrict__ Wsm,
                                        const float* __restrict__ Wsrc, int tid) {
    for (int idx = tid; idx < NG * KC; idx += TPB) {
        int k  = idx / NG;
        int nn = idx - k * NG;
        Wsm[nn * KC + k] = Wsrc[idx];
    }
}

// One LSTM gate GEMV step for 2 columns (n0=tid, n1=tid+256) x 4 rows.
// g[c][m] = b_c + x_m*wih_c + sum_k hs[m][k]*W[k][n_c]
__device__ __forceinline__ void gate_step(
    const float* __restrict__ hs,
    const float* __restrict__ Wsm,
    const float* __restrict__ Wg,     // global weight matrix (for k >= KC)
    int n0,
    float b0, float b1, float wih0, float wih1,
    float x0, float x1, float x2, float x3,
    float g[2][4])
{
    const int n1 = n0 + 256;

    // Prefetch L2 tail weights into registers first (hide ~250cyc L2 latency
    // under the smem mainloop below).
    float wt0[KT], wt1[KT];
#pragma unroll
    for (int i = 0; i < KT; i++) {
        wt0[i] = __ldg(Wg + (size_t)(KC + i) * NG + n0);
        wt1[i] = __ldg(Wg + (size_t)(KC + i) * NG + n1);
    }

    u64 a[2][4];
    F2U t;
    t.f = make_float2(b0 + x0 * wih0, 0.f); a[0][0] = t.u;
    t.f = make_float2(b0 + x1 * wih0, 0.f); a[0][1] = t.u;
    t.f = make_float2(b0 + x2 * wih0, 0.f); a[0][2] = t.u;
    t.f = make_float2(b0 + x3 * wih0, 0.f); a[0][3] = t.u;
    t.f = make_float2(b1 + x0 * wih1, 0.f); a[1][0] = t.u;
    t.f = make_float2(b1 + x1 * wih1, 0.f); a[1][1] = t.u;
    t.f = make_float2(b1 + x2 * wih1, 0.f); a[1][2] = t.u;
    t.f = make_float2(b1 + x3 * wih1, 0.f); a[1][3] = t.u;

    const ulonglong2* wp0 = reinterpret_cast<const ulonglong2*>(Wsm + n0 * KC);
    const ulonglong2* wp1 = reinterpret_cast<const ulonglong2*>(Wsm + n1 * KC);
    const ulonglong2* h0p = reinterpret_cast<const ulonglong2*>(hs);
    const ulonglong2* h1p = reinterpret_cast<const ulonglong2*>(hs + H_);
    const ulonglong2* h2p = reinterpret_cast<const ulonglong2*>(hs + 2 * H_);
    const ulonglong2* h3p = reinterpret_cast<const ulonglong2*>(hs + 3 * H_);

#pragma unroll
    for (int i = 0; i < KC / 4; i++) {
        ulonglong2 w0 = wp0[i], w1 = wp1[i];
        ulonglong2 h0 = h0p[i], h1 = h1p[i], h2 = h2p[i], h3 = h3p[i];
        fma2(a[0][0], h0.x, w0.x); fma2(a[0][0], h0.y, w0.y);
        fma2(a[0][1], h1.x, w0.x); fma2(a[0][1], h1.y, w0.y);
        fma2(a[0][2], h2.x, w0.x); fma2(a[0][2], h2.y, w0.y);
        fma2(a[0][3], h3.x, w0.x); fma2(a[0][3], h3.y, w0.y);
        fma2(a[1][0], h0.x, w1.x); fma2(a[1][0], h0.y, w1.y);
        fma2(a[1][1], h1.x, w1.x); fma2(a[1][1], h1.y, w1.y);
        fma2(a[1][2], h2.x, w1.x); fma2(a[1][2], h2.y, w1.y);
        fma2(a[1][3], h3.x, w1.x); fma2(a[1][3], h3.y, w1.y);
    }

    // Tail k in [KC, 128), weights from prefetched registers.
#pragma unroll
    for (int i = 0; i < KT / 4; i++) {
        const int k = KC + 4 * i;
        F2U wa0, wb0, wa1, wb1;
        wa0.f = make_float2(wt0[4 * i],     wt0[4 * i + 1]);
        wb0.f = make_float2(wt0[4 * i + 2], wt0[4 * i + 3]);
        wa1.f = make_float2(wt1[4 * i],     wt1[4 * i + 1]);
        wb1.f = make_float2(wt1[4 * i + 2], wt1[4 * i + 3]);
        ulonglong2 h0 = *reinterpret_cast<const ulonglong2*>(hs + 0 * H_ + k);
        ulonglong2 h1 = *reinterpret_cast<const ulonglong2*>(hs + 1 * H_ + k);
        ulonglong2 h2 = *reinterpret_cast<const ulonglong2*>(hs + 2 * H_ + k);
        ulonglong2 h3 = *reinterpret_cast<const ulonglong2*>(hs + 3 * H_ + k);
        fma2(a[0][0], h0.x, wa0.u); fma2(a[0][0], h0.y, wb0.u);
        fma2(a[0][1], h1.x, wa0.u); fma2(a[0][1], h1.y, wb0.u);
        fma2(a[0][2], h2.x, wa0.u); fma2(a[0][2], h2.y, wb0.u);
        fma2(a[0][3], h3.x, wa0.u); fma2(a[0][3], h3.y, wb0.u);
        fma2(a[1][0], h0.x, wa1.u); fma2(a[1][0], h0.y, wb1.u);
        fma2(a[1][1], h1.x, wa1.u); fma2(a[1][1], h1.y, wb1.u);
        fma2(a[1][2], h2.x, wa1.u); fma2(a[1][2], h2.y, wb1.u);
        fma2(a[1][3], h3.x, wa1.u); fma2(a[1][3], h3.y, wb1.u);
    }

#pragma unroll
    for (int c = 0; c < 2; c++)
#pragma unroll
        for (int m = 0; m < 4; m++) {
            t.u = a[c][m];
            g[c][m] = t.f.x + t.f.y;
        }
}

__global__ __launch_bounds__(TPB, 1)
void seq2seq_kernel(
    const float* __restrict__ inputs,
    const float* __restrict__ Wih_e, const float* __restrict__ Whh_e, const float* __restrict__ b_e,
    const float* __restrict__ Wih_d, const float* __restrict__ Whh_d, const float* __restrict__ b_d,
    const float* __restrict__ We,    const float* __restrict__ Wd,
    const float* __restrict__ Wv,    const float* __restrict__ Wf,    const float* __restrict__ bf,
    float* __restrict__ out, int write_attn)
{
    extern __shared__ float smf[];
    float* Wsm     = smf;                      // NG*KC   = 51200
    float* hs      = Wsm + NG * KC;            // R_*H_   = 512   (16B aligned)
    float* gfo     = hs + R_ * H_;             // 2*R_*H_ = 1024  (f,o staging)
    float* xs      = gfo + 2 * R_ * H_;        // R_      = 4
    float* xenc    = xs + R_;                  // R_*S_   = 56
    float* attn    = xenc + R_ * S_;           // R_*S_   = 56
    float* attnAcc = attn + R_ * S_;           // R_*S_   = 56
    float* red     = attnAcc + R_ * S_;        // R_*S_*4 = 224
    float* ctx     = red + R_ * S_ * 4;        // R_*H_   = 512
    // total 53644 floats = 214576 bytes

    const int tid   = threadIdx.x;
    const int lane  = tid & 31;
    const int wg    = (tid >> 5) & 3;
    const int cta   = blockIdx.x;
    const bool lower = (tid < 128);
    const int j     = tid & 127;

    // ---- init + stage encoder weights ----
    stage_w(Wsm, Whh_e, tid);
    if (tid < R_ * S_) {
        attnAcc[tid] = 0.f;
        int mm = tid / S_, tt = tid - mm * S_;
        xenc[tid] = inputs[(cta * R_ + mm) * S_ + tt];
    }
    if (tid < R_) xs[tid] = inputs[(cta * R_ + tid) * S_ + (S_ - 1)];
    for (int idx = tid; idx < R_ * H_; idx += TPB) hs[idx] = 0.f;

    float creg[R_] = {0.f, 0.f, 0.f, 0.f};     // c-state (lower threads: unit j, rows 0..3)

    const float be0 = b_e[tid],  be1 = b_e[tid + 256];
    const float we0 = Wih_e[tid], we1 = Wih_e[tid + 256];
    const float wv_j = Wv[j];
    const float wf_j = Wf[j];
    const float bf0  = bf[0];
    __syncthreads();

    // ================= Encoder: 14 steps =================
    for (int t = 0; t < S_; t++) {
        float g[2][4];
        gate_step(hs, Wsm, Whh_e, tid, be0, be1, we0, we1,
                  xenc[0 * S_ + t], xenc[1 * S_ + t],
                  xenc[2 * S_ + t], xenc[3 * S_ + t], g);
        if (!lower) {
#pragma unroll
            for (int m = 0; m < 4; m++) {
                gfo[m * H_ + j]       = g[0][m];  // f gate
                gfo[512 + m * H_ + j] = g[1][m];  // o gate
            }
        }
        __syncthreads();
        if (lower) {
#pragma unroll
            for (int m = 0; m < 4; m++) {
                float gi = g[0][m], gg = g[1][m];
                float gf = gfo[m * H_ + j], go = gfo[512 + m * H_ + j];
                float c  = sigm(gf) * creg[m] + sigm(gi) * tanh_(gg);
                float h  = sigm(go) * tanh_(c);
                creg[m] = c;
                hs[m * H_ + j] = h;
                g_enc[((size_t)(cta * R_ + m)) * S_ * H_ + t * H_ + j] = h;
            }
        }
        __syncthreads();
    }

    // ---- restage decoder weights ----
    stage_w(Wsm, Whh_d, tid);

    // ---- encProj[t][j] = sum_k enc[t][k] * We[k][j] (once; reused 8x) ----
    for (int cell = tid; cell < R_ * H_; cell += TPB) {
        int m = cell >> 7, jj = cell & 127;
        const float* eb = g_enc + ((size_t)(cta * R_ + m)) * S_ * H_;
        float acc[S_];
#pragma unroll
        for (int t = 0; t < S_; t++) acc[t] = 0.f;
#pragma unroll 4
        for (int k = 0; k < H_; k++) {
            float we = __ldg(We + k * H_ + jj);
#pragma unroll
            for (int t = 0; t < S_; t++) acc[t] += __ldg(eb + t * H_ + k) * we;
        }
        float* pb = g_encProj + ((size_t)(cta * R_ + m)) * S_ * H_;
#pragma unroll
        for (int t = 0; t < S_; t++) pb[t * H_ + jj] = acc[t];
    }

    const float bd0 = b_d[tid],  bd1 = b_d[tid + 256];
    const float wd0 = Wih_d[tid], wd1 = Wih_d[tid + 256];
    __syncthreads();

    // ================= Decoder: 8 steps =================
    for (int s = 0; s < TLEN; s++) {
        // hWd[m][j] = h[m] @ Wd
        for (int cell = tid; cell < R_ * H_; cell += TPB) {
            int m = cell >> 7, jj = cell & 127;
            float acc = 0.f;
#pragma unroll 8
            for (int k = 0; k < H_; k++)
                acc += hs[m * H_ + k] * __ldg(Wd + k * H_ + jj);
            ctx[cell] = acc;
        }
        __syncthreads();

        // scores[m][t] = sum_j tanh(encProj + hWd) * Wv
#pragma unroll
        for (int pass = 0; pass < 2; pass++) {
            int m = (tid >> 7) + 2 * pass;
            float hwd = ctx[m * H_ + j];
            const float* ep = g_encProj + ((size_t)(cta * R_ + m)) * S_ * H_;
#pragma unroll
            for (int t = 0; t < S_; t++) {
                float v = tanh_(ep[t * H_ + j] + hwd) * wv_j;
                v = warpsum(v);
                if (lane == 0) red[(m * S_ + t) * 4 + wg] = v;
            }
        }
        __syncthreads();
        if (tid < R_ * S_) {
            int b4 = tid * 4;
            attn[tid] = red[b4] + red[b4 + 1] + red[b4 + 2] + red[b4 + 3];
        }
        __syncthreads();
        if (tid < R_) {  // softmax over S + accumulate total_attn (row = tid)
            float mx = attn[tid * S_];
#pragma unroll
            for (int t = 1; t < S_; t++) mx = fmaxf(mx, attn[tid * S_ + t]);
            float ssum = 0.f, ex[S_];
#pragma unroll
            for (int t = 0; t < S_; t++) { ex[t] = __expf(attn[tid * S_ + t] - mx); ssum += ex[t]; }
            float inv = __fdividef(1.f, ssum);
#pragma unroll
            for (int t = 0; t < S_; t++) {
                float a_ = ex[t] * inv;
                attn[tid * S_ + t] = a_;
                attnAcc[tid * S_ + t] += a_;
            }
        }
        __syncthreads();
        // context[m][j] = sum_t attn * enc
        for (int cell = tid; cell < R_ * H_; cell += TPB) {
            int m = cell >> 7, jj = cell & 127;
            const float* eb = g_enc + ((size_t)(cta * R_ + m)) * S_ * H_;
            float acc = 0.f;
#pragma unroll
            for (int t = 0; t < S_; t++) acc += attn[m * S_ + t] * __ldg(eb + t * H_ + jj);
            ctx[cell] = acc;
        }
        __syncthreads();

        // inner decoder LSTM: 129 scalar-input steps
        for (int js = 0; js < H_ + 1; js++) {
            float x0, x1, x2, x3;
            if (js < H_) {
                x0 = ctx[js]; x1 = ctx[H_ + js]; x2 = ctx[2 * H_ + js]; x3 = ctx[3 * H_ + js];
            } else {
                x0 = xs[0]; x1 = xs[1]; x2 = xs[2]; x3 = xs[3];
            }
            float g[2][4];
            gate_step(hs, Wsm, Whh_d, tid, bd0, bd1, wd0, wd1, x0, x1, x2, x3, g);
            if (!lower) {
#pragma unroll
                for (int m = 0; m < 4; m++) {
                    gfo[m * H_ + j]       = g[0][m];
                    gfo[512 + m * H_ + j] = g[1][m];
                }
            }
            __syncthreads();
            if (lower) {
#pragma unroll
                for (int m = 0; m < 4; m++) {
                    float gi = g[0][m], gg = g[1][m];
                    float gf = gfo[m * H_ + j], go = gfo[512 + m * H_ + j];
                    float c  = sigm(gf) * creg[m] + sigm(gi) * tanh_(gg);
                    float h  = sigm(go) * tanh_(c);
                    creg[m] = c;
                    hs[m * H_ + j] = h;
                }
            }
            __syncthreads();
        }

        // out = h @ Wf + bf ; feed back as next x
#pragma unroll
        for (int pass = 0; pass < 2; pass++) {
            int m = (tid >> 7) + 2 * pass;
            float v = hs[m * H_ + j] * wf_j;
            v = warpsum(v);
            if (lane == 0) red[m * 4 + wg] = v;
        }
        __syncthreads();
        if (tid < R_) {
            float o = red[tid * 4] + red[tid * 4 + 1] + red[tid * 4 + 2] + red[tid * 4 + 3] + bf0;
            out[(cta * R_ + tid) * TLEN + s] = o;
            xs[tid] = o;
        }
        __syncthreads();
    }

    if (write_attn) {
        for (int idx = tid; idx < R_ * S_; idx += TPB)
            out[B_ * TLEN + (cta * R_ + idx / S_) * S_ + (idx % S_)] = attnAcc[idx];
    }
}

extern "C" void kernel_launch(void* const* d_in, const int* in_sizes, int n_in,
                              void* d_out, int out_size) {
    const float* inputs = (const float*)d_in[0];
    const int off = (n_in >= 13 && in_sizes[1] == 1) ? 2 : 1;
    const float* Wih_e = (const float*)d_in[off + 0];
    const float* Whh_e = (const float*)d_in[off + 1];
    const float* b_e   = (const float*)d_in[off + 2];
    const float* Wih_d = (const float*)d_in[off + 3];
    const float* Whh_d = (const float*)d_in[off + 4];
    const float* b_d   = (const float*)d_in[off + 5];
    const float* We    = (const float*)d_in[off + 6];
    const float* Wd    = (const float*)d_in[off + 7];
    const float* Wv    = (const float*)d_in[off + 8];
    const float* Wf    = (const float*)d_in[off + 9];
    const float* bf    = (const float*)d_in[off + 10];

    const int smem_floats = NG * KC + R_ * H_ + 2 * R_ * H_ + R_ + 3 * R_ * S_
                          + R_ * S_ * 4 + R_ * H_;
    const int smem_bytes = smem_floats * (int)sizeof(float);  // 214576

    cudaFuncSetAttribute(seq2seq_kernel,
                         cudaFuncAttributeMaxDynamicSharedMemorySize, smem_bytes);

    const int write_attn = (out_size >= B_ * TLEN + B_ * S_) ? 1 : 0;

    seq2seq_kernel<<<NCTA, TPB, smem_bytes>>>(
        inputs, Wih_e, Whh_e, b_e, Wih_d, Whh_d, b_d,
        We, Wd, Wv, Wf, bf, (float*)d_out, write_attn);
}

// round 7
// speedup vs baseline: 1.5537x; 1.1867x over previous
#include <cuda_runtime.h>

// ---------------------------------------------------------------------------
// AttentionSeq2SeqModel: B=512, S=14, H=128, IN=1, target_len=8
// out = [B,8,1] outputs followed by [B,14,1] total_attn (fp32).
//
// R7: 128 CTAs x 256 threads, 4 rows/CTA. Gate-pair thread mapping:
// thread pair (2u,2u+1) owns unit u's gates (i,g)/(f,o); cross-gate product
// exchanged via __shfl_up -> ONE barrier per LSTM step with double-buffered h.
// Whh k in [0,88) in smem (stride 92, conflict-free), k in [88,128) resident
// in registers as packed f32x2 (loaded once per phase). fma.rn.f32x2 mainloop.
// ---------------------------------------------------------------------------

#define B_    512
#define S_    14
#define H_    128
#define NG    512
#define R_    4
#define TPB   256
#define NCTA  128
#define KS    88          // k-rows in smem
#define WSTR  92          // smem stride (92 % 8 == 4 -> conflict-free LDS.128)
#define KR    40          // k-rows in registers
#define KRP   (KR / 2)    // packed f32x2 count per column
#define TLEN  8

typedef unsigned long long u64;

__device__ float g_enc[B_ * S_ * H_];
__device__ float g_encProj[B_ * S_ * H_];

union F2U { float2 f; u64 u; };

__device__ __forceinline__ void fma2(u64 &acc, u64 a, u64 b) {
    asm("fma.rn.f32x2 %0, %1, %2, %0;" : "+l"(acc) : "l"(a), "l"(b));
}
__device__ __forceinline__ float sigm(float x) {
    return __fdividef(1.0f, 1.0f + __expf(-x));
}
__device__ __forceinline__ float tanh_(float x) {
    return __fdividef(2.0f, 1.0f + __expf(-2.0f * x)) - 1.0f;
}
__device__ __forceinline__ float warpsum(float v) {
    v += __shfl_xor_sync(0xffffffffu, v, 16);
    v += __shfl_xor_sync(0xffffffffu, v, 8);
    v += __shfl_xor_sync(0xffffffffu, v, 4);
    v += __shfl_xor_sync(0xffffffffu, v, 2);
    v += __shfl_xor_sync(0xffffffffu, v, 1);
    return v;
}

// thread t, slot c -> gate column. even t: (i_u, g_u); odd t: (f_u, o_u), u=t>>1
__device__ __forceinline__ int colmap(int t, int c) {
    return ((t & 1) << 7) + (t >> 1) + (c << 8);
}

// Wsm[(c*256 + t)*WSTR + k] = W[k][colmap(t,c)], k < KS
__device__ __forceinline__ void stage_w(float* __restrict__ Wsm,
                                        const float* __restrict__ W, int tid) {
    for (int idx = tid; idx < NG * KS; idx += TPB) {
        int k    = idx >> 9;
        int slot = idx & 511;
        int c = slot >> 8, t = slot & 255;
        Wsm[slot * WSTR + k] = W[(size_t)k * NG + colmap(t, c)];
    }
}

// register tail: k in [KS,128), packed (k, k+1) into f32x2
__device__ __forceinline__ void load_tail(u64 wrp[2][KRP],
                                          const float* __restrict__ W, int tid) {
#pragma unroll
    for (int c = 0; c < 2; c++) {
        const int col = colmap(tid, c);
#pragma unroll
        for (int i = 0; i < KRP; i++) {
            F2U v;
            v.f.x = __ldg(W + (size_t)(KS + 2 * i)     * NG + col);
            v.f.y = __ldg(W + (size_t)(KS + 2 * i + 1) * NG + col);
            wrp[c][i] = v.u;
        }
    }
}

// gate GEMV: ga[m] = b0 + x_m*wih0 + sum_k h[m][k] W[k][col0]; gb likewise col1
__device__ __forceinline__ void gate_gemv(
    const float* __restrict__ hsR,
    const float* __restrict__ w0, const float* __restrict__ w1,
    const u64 wrp[2][KRP],
    float b0, float b1, float wih0, float wih1,
    float x0, float x1, float x2, float x3,
    float ga[4], float gb[4])
{
    u64 a0[4], a1[4];
    F2U t;
    t.f = make_float2(fmaf(x0, wih0, b0), 0.f); a0[0] = t.u;
    t.f = make_float2(fmaf(x1, wih0, b0), 0.f); a0[1] = t.u;
    t.f = make_float2(fmaf(x2, wih0, b0), 0.f); a0[2] = t.u;
    t.f = make_float2(fmaf(x3, wih0, b0), 0.f); a0[3] = t.u;
    t.f = make_float2(fmaf(x0, wih1, b1), 0.f); a1[0] = t.u;
    t.f = make_float2(fmaf(x1, wih1, b1), 0.f); a1[1] = t.u;
    t.f = make_float2(fmaf(x2, wih1, b1), 0.f); a1[2] = t.u;
    t.f = make_float2(fmaf(x3, wih1, b1), 0.f); a1[3] = t.u;

    const ulonglong2* wp0 = reinterpret_cast<const ulonglong2*>(w0);
    const ulonglong2* wp1 = reinterpret_cast<const ulonglong2*>(w1);
    const ulonglong2* h0p = reinterpret_cast<const ulonglong2*>(hsR);
    const ulonglong2* h1p = reinterpret_cast<const ulonglong2*>(hsR + H_);
    const ulonglong2* h2p = reinterpret_cast<const ulonglong2*>(hsR + 2 * H_);
    const ulonglong2* h3p = reinterpret_cast<const ulonglong2*>(hsR + 3 * H_);

#pragma unroll
    for (int i = 0; i < KS / 4; i++) {
        ulonglong2 w0v = wp0[i], w1v = wp1[i];
        ulonglong2 h0 = h0p[i], h1 = h1p[i], h2 = h2p[i], h3 = h3p[i];
        fma2(a0[0], h0.x, w0v.x); fma2(a0[0], h0.y, w0v.y);
        fma2(a0[1], h1.x, w0v.x); fma2(a0[1], h1.y, w0v.y);
        fma2(a0[2], h2.x, w0v.x); fma2(a0[2], h2.y, w0v.y);
        fma2(a0[3], h3.x, w0v.x); fma2(a0[3], h3.y, w0v.y);
        fma2(a1[0], h0.x, w1v.x); fma2(a1[0], h0.y, w1v.y);
        fma2(a1[1], h1.x, w1v.x); fma2(a1[1], h1.y, w1v.y);
        fma2(a1[2], h2.x, w1v.x); fma2(a1[2], h2.y, w1v.y);
        fma2(a1[3], h3.x, w1v.x); fma2(a1[3], h3.y, w1v.y);
    }
#pragma unroll
    for (int i = 0; i < KR / 4; i++) {
        const int ib = KS / 4 + i;   // (KS + 4i)/4
        u64 wa0 = wrp[0][2 * i], wb0 = wrp[0][2 * i + 1];
        u64 wa1 = wrp[1][2 * i], wb1 = wrp[1][2 * i + 1];
        ulonglong2 h0 = h0p[ib], h1 = h1p[ib], h2 = h2p[ib], h3 = h3p[ib];
        fma2(a0[0], h0.x, wa0); fma2(a0[0], h0.y, wb0);
        fma2(a0[1], h1.x, wa0); fma2(a0[1], h1.y, wb0);
        fma2(a0[2], h2.x, wa0); fma2(a0[2], h2.y, wb0);
        fma2(a0[3], h3.x, wa0); fma2(a0[3], h3.y, wb0);
        fma2(a1[0], h0.x, wa1); fma2(a1[0], h0.y, wb1);
        fma2(a1[1], h1.x, wa1); fma2(a1[1], h1.y, wb1);
        fma2(a1[2], h2.x, wa1); fma2(a1[2], h2.y, wb1);
        fma2(a1[3], h3.x, wa1); fma2(a1[3], h3.y, wb1);
    }
#pragma unroll
    for (int m = 0; m < 4; m++) {
        t.u = a0[m]; ga[m] = t.f.x + t.f.y;
        t.u = a1[m]; gb[m] = t.f.x + t.f.y;
    }
}

__global__ __launch_bounds__(TPB, 1)
void seq2seq_kernel(
    const float* __restrict__ inputs,
    const float* __restrict__ Wih_e, const float* __restrict__ Whh_e, const float* __restrict__ b_e,
    const float* __restrict__ Wih_d, const float* __restrict__ Whh_d, const float* __restrict__ b_d,
    const float* __restrict__ We,    const float* __restrict__ Wd,
    const float* __restrict__ Wv,    const float* __restrict__ Wf,    const float* __restrict__ bf,
    float* __restrict__ out, int write_attn)
{
    extern __shared__ float smf[];
    float* Wsm     = smf;                        // 512*WSTR = 47104
    float* hsA     = Wsm + NG * WSTR;            // 512
    float* hsB     = hsA + R_ * H_;              // 512
    float* ctx     = hsB + R_ * H_;              // 512
    float* xs      = ctx + R_ * H_;              // 4
    float* xenc    = xs + R_;                    // 56
    float* attn    = xenc + R_ * S_;             // 56
    float* attnAcc = attn + R_ * S_;             // 56
    float* red     = attnAcc + R_ * S_;          // 224
    // total 48524 floats = 194096 B

    const int tid  = threadIdx.x;
    const int lane = tid & 31;
    const int wg   = (tid >> 5) & 3;
    const int cta  = blockIdx.x;
    const int u    = tid >> 1;
    const int par  = tid & 1;
    const int j    = tid & 127;

    const int c0 = colmap(tid, 0), c1 = colmap(tid, 1);
    const float* w0p = Wsm + tid * WSTR;
    const float* w1p = Wsm + (256 + tid) * WSTR;

    u64 wrp[2][KRP];

    // ---- init ----
    stage_w(Wsm, Whh_e, tid);
    load_tail(wrp, Whh_e, tid);
    if (tid < R_ * S_) {
        attnAcc[tid] = 0.f;
        int mm = tid / S_, tt = tid - mm * S_;
        xenc[tid] = inputs[(cta * R_ + mm) * S_ + tt];
    }
    if (tid < R_) xs[tid] = inputs[(cta * R_ + tid) * S_ + (S_ - 1)];
    for (int idx = tid; idx < R_ * H_; idx += TPB) hsA[idx] = 0.f;

    float creg[R_] = {0.f, 0.f, 0.f, 0.f};  // odd threads: c-state of unit u, rows 0..3
    float* hsR = hsA;
    float* hsW = hsB;

    const float be0 = b_e[c0],   be1 = b_e[c1];
    const float we0 = Wih_e[c0], we1 = Wih_e[c1];
    const float wv_j = Wv[j];
    const float wf_j = Wf[j];
    const float bf0  = bf[0];
    __syncthreads();

    // ================= Encoder: 14 steps =================
    for (int t = 0; t < S_; t++) {
        float ga[4], gb[4];
        gate_gemv(hsR, w0p, w1p, wrp, be0, be1, we0, we1,
                  xenc[0 * S_ + t], xenc[1 * S_ + t],
                  xenc[2 * S_ + t], xenc[3 * S_ + t], ga, gb);
        float pv[4] = {0.f, 0.f, 0.f, 0.f};
        if (!par) {
#pragma unroll
            for (int m = 0; m < 4; m++) pv[m] = sigm(ga[m]) * tanh_(gb[m]);
        }
        float q[4];
#pragma unroll
        for (int m = 0; m < 4; m++) q[m] = __shfl_up_sync(0xffffffffu, pv[m], 1);
        if (par) {
#pragma unroll
            for (int m = 0; m < 4; m++) {
                float c = sigm(ga[m]) * creg[m] + q[m];
                creg[m] = c;
                float h = sigm(gb[m]) * tanh_(c);
                hsW[m * H_ + u] = h;
                g_enc[((size_t)(cta * R_ + m)) * S_ * H_ + t * H_ + u] = h;
            }
        }
        __syncthreads();
        float* tmp = hsR; hsR = hsW; hsW = tmp;
    }

    // ---- restage for decoder ----
    stage_w(Wsm, Whh_d, tid);
    load_tail(wrp, Whh_d, tid);

    // ---- encProj[t][j] = sum_k enc[t][k] * We[k][j] (once; reused 8x) ----
    for (int cell = tid; cell < R_ * H_; cell += TPB) {
        int m = cell >> 7, jj = cell & 127;
        const float* eb = g_enc + ((size_t)(cta * R_ + m)) * S_ * H_;
        float acc[S_];
#pragma unroll
        for (int t = 0; t < S_; t++) acc[t] = 0.f;
#pragma unroll 4
        for (int k = 0; k < H_; k++) {
            float we = __ldg(We + k * H_ + jj);
#pragma unroll
            for (int t = 0; t < S_; t++) acc[t] += __ldg(eb + t * H_ + k) * we;
        }
        float* pb = g_encProj + ((size_t)(cta * R_ + m)) * S_ * H_;
#pragma unroll
        for (int t = 0; t < S_; t++) pb[t * H_ + jj] = acc[t];
    }

    const float bd0 = b_d[c0],   bd1 = b_d[c1];
    const float wd0 = Wih_d[c0], wd1 = Wih_d[c1];
    __syncthreads();

    // ================= Decoder: 8 steps =================
    for (int s = 0; s < TLEN; s++) {
        // hWd[m][j] = h[m] @ Wd
        for (int cell = tid; cell < R_ * H_; cell += TPB) {
            int m = cell >> 7, jj = cell & 127;
            float acc = 0.f;
#pragma unroll 8
            for (int k = 0; k < H_; k++)
                acc += hsR[m * H_ + k] * __ldg(Wd + k * H_ + jj);
            ctx[cell] = acc;
        }
        __syncthreads();

        // scores[m][t] = sum_j tanh(encProj + hWd) * Wv
#pragma unroll
        for (int pass = 0; pass < 2; pass++) {
            int m = (tid >> 7) + 2 * pass;
            float hwd = ctx[m * H_ + j];
            const float* ep = g_encProj + ((size_t)(cta * R_ + m)) * S_ * H_;
#pragma unroll
            for (int t = 0; t < S_; t++) {
                float v = tanh_(ep[t * H_ + j] + hwd) * wv_j;
                v = warpsum(v);
                if (lane == 0) red[(m * S_ + t) * 4 + wg] = v;
            }
        }
        __syncthreads();
        if (tid < R_ * S_) {
            int b4 = tid * 4;
            attn[tid] = red[b4] + red[b4 + 1] + red[b4 + 2] + red[b4 + 3];
        }
        __syncthreads();
        if (tid < R_) {
            float mx = attn[tid * S_];
#pragma unroll
            for (int t = 1; t < S_; t++) mx = fmaxf(mx, attn[tid * S_ + t]);
            float ssum = 0.f, ex[S_];
#pragma unroll
            for (int t = 0; t < S_; t++) { ex[t] = __expf(attn[tid * S_ + t] - mx); ssum += ex[t]; }
            float inv = __fdividef(1.f, ssum);
#pragma unroll
            for (int t = 0; t < S_; t++) {
                float a_ = ex[t] * inv;
                attn[tid * S_ + t] = a_;
                attnAcc[tid * S_ + t] += a_;
            }
        }
        __syncthreads();
        // context[m][j] = sum_t attn * enc
        for (int cell = tid; cell < R_ * H_; cell += TPB) {
            int m = cell >> 7, jj = cell & 127;
            const float* eb = g_enc + ((size_t)(cta * R_ + m)) * S_ * H_;
            float acc = 0.f;
#pragma unroll
            for (int t = 0; t < S_; t++) acc += attn[m * S_ + t] * __ldg(eb + t * H_ + jj);
            ctx[cell] = acc;
        }
        __syncthreads();

        // inner decoder LSTM: 129 scalar-input steps, ONE barrier each
        for (int js = 0; js < H_ + 1; js++) {
            float x0, x1, x2, x3;
            if (js < H_) {
                x0 = ctx[js]; x1 = ctx[H_ + js]; x2 = ctx[2 * H_ + js]; x3 = ctx[3 * H_ + js];
            } else {
                x0 = xs[0]; x1 = xs[1]; x2 = xs[2]; x3 = xs[3];
            }
            float ga[4], gb[4];
            gate_gemv(hsR, w0p, w1p, wrp, bd0, bd1, wd0, wd1, x0, x1, x2, x3, ga, gb);
            float pv[4] = {0.f, 0.f, 0.f, 0.f};
            if (!par) {
#pragma unroll
                for (int m = 0; m < 4; m++) pv[m] = sigm(ga[m]) * tanh_(gb[m]);
            }
            float q[4];
#pragma unroll
            for (int m = 0; m < 4; m++) q[m] = __shfl_up_sync(0xffffffffu, pv[m], 1);
            if (par) {
#pragma unroll
                for (int m = 0; m < 4; m++) {
                    float c = sigm(ga[m]) * creg[m] + q[m];
                    creg[m] = c;
                    hsW[m * H_ + u] = sigm(gb[m]) * tanh_(c);
                }
            }
            __syncthreads();
            float* tmp = hsR; hsR = hsW; hsW = tmp;
        }

        // out = h @ Wf + bf ; feed back as next x
#pragma unroll
        for (int pass = 0; pass < 2; pass++) {
            int m = (tid >> 7) + 2 * pass;
            float v = hsR[m * H_ + j] * wf_j;
            v = warpsum(v);
            if (lane == 0) red[m * 4 + wg] = v;
        }
        __syncthreads();
        if (tid < R_) {
            float o = red[tid * 4] + red[tid * 4 + 1] + red[tid * 4 + 2] + red[tid * 4 + 3] + bf0;
            out[(cta * R_ + tid) * TLEN + s] = o;
            xs[tid] = o;
        }
        __syncthreads();
    }

    if (write_attn) {
        for (int idx = tid; idx < R_ * S_; idx += TPB)
            out[B_ * TLEN + (cta * R_ + idx / S_) * S_ + (idx % S_)] = attnAcc[idx];
    }
}

extern "C" void kernel_launch(void* const* d_in, const int* in_sizes, int n_in,
                              void* d_out, int out_size) {
    const float* inputs = (const float*)d_in[0];
    const int off = (n_in >= 13 && in_sizes[1] == 1) ? 2 : 1;
    const float* Wih_e = (const float*)d_in[off + 0];
    const float* Whh_e = (const float*)d_in[off + 1];
    const float* b_e   = (const float*)d_in[off + 2];
    const float* Wih_d = (const float*)d_in[off + 3];
    const float* Whh_d = (const float*)d_in[off + 4];
    const float* b_d   = (const float*)d_in[off + 5];
    const float* We    = (const float*)d_in[off + 6];
    const float* Wd    = (const float*)d_in[off + 7];
    const float* Wv    = (const float*)d_in[off + 8];
    const float* Wf    = (const float*)d_in[off + 9];
    const float* bf    = (const float*)d_in[off + 10];

    const int smem_floats = NG * WSTR + 3 * R_ * H_ + R_ + 3 * R_ * S_ + R_ * S_ * 4;
    const int smem_bytes = smem_floats * (int)sizeof(float);  // 194096

    cudaFuncSetAttribute(seq2seq_kernel,
                         cudaFuncAttributeMaxDynamicSharedMemorySize, smem_bytes);

    const int write_attn = (out_size >= B_ * TLEN + B_ * S_) ? 1 : 0;

    seq2seq_kernel<<<NCTA, TPB, smem_bytes>>>(
        inputs, Wih_e, Whh_e, b_e, Wih_d, Whh_d, b_d,
        We, Wd, Wv, Wf, bf, (float*)d_out, write_attn);
}

// round 8
// speedup vs baseline: 1.8058x; 1.1623x over previous
#include <cuda_runtime.h>

// ---------------------------------------------------------------------------
// AttentionSeq2SeqModel: B=512, S=14, H=128, IN=1, target_len=8
// out = [B,8,1] outputs then [B,14,1] total_attn (fp32).
//
// R8: split-K. 128 CTAs x 256 threads, 4 rows/CTA. Thread (q,p) computes the
// k in [64p,64p+64) partial of ALL 4 gates of unit q (cols q,q+128,q+256,
// q+384) for 4 rows. Partials exchanged via smem (stride-12, conflict-free);
// each thread finishes rows {2p,2p+1}. Halves h-broadcast L1 slots.
// Weights: 24 k-rows/half in regs (96 regs), 40/half in smem (stride 44,
// conflict-free LDS.128). Packed fma.rn.f32x2 throughout.
// ---------------------------------------------------------------------------

#define B_    512
#define S_    14
#define H_    128
#define NG    512
#define R_    4
#define TPB   256
#define NCTA  128
#define KRH   24          // k-rows per half in registers
#define KSH   40          // k-rows per half in smem
#define WSTR  44          // smem slot stride (44%8==4, 176B: conflict-free)
#define PSTR  12          // partial-exchange stride (48B aligned, conflict-free)
#define TLEN  8

typedef unsigned long long u64;

__device__ float g_enc[B_ * S_ * H_];
__device__ float g_encProj[B_ * S_ * H_];

union F2U { float2 f; u64 u; };

__device__ __forceinline__ void fma2(u64 &acc, u64 a, u64 b) {
    asm("fma.rn.f32x2 %0, %1, %2, %0;" : "+l"(acc) : "l"(a), "l"(b));
}
__device__ __forceinline__ float sigm(float x) {
    return __fdividef(1.0f, 1.0f + __expf(-x));
}
__device__ __forceinline__ float tanh_(float x) {
    return __fdividef(2.0f, 1.0f + __expf(-2.0f * x)) - 1.0f;
}
__device__ __forceinline__ float warpsum(float v) {
    v += __shfl_xor_sync(0xffffffffu, v, 16);
    v += __shfl_xor_sync(0xffffffffu, v, 8);
    v += __shfl_xor_sync(0xffffffffu, v, 4);
    v += __shfl_xor_sync(0xffffffffu, v, 2);
    v += __shfl_xor_sync(0xffffffffu, v, 1);
    return v;
}

// smem weight slot for (gate c, half p, unit q)
__device__ __forceinline__ int wslot(int c, int p, int q) {
    return (c * 2 + p) * 128 + q;
}

// Stage Wsm[slot][i] = W[p*64 + KRH + i][c*128 + q], i < KSH.
__device__ __forceinline__ void stage_w(float* __restrict__ Wsm,
                                        const float* __restrict__ W, int tid) {
    for (int idx = tid; idx < 1024 * KSH; idx += TPB) {
        int i    = idx >> 10;
        int slot = idx & 1023;
        int q  = slot & 127;
        int g2 = slot >> 7;
        int c  = g2 >> 1;
        int p  = g2 & 1;
        int k  = p * 64 + KRH + i;
        Wsm[slot * WSTR + i] = W[(size_t)k * NG + c * 128 + q];
    }
}

// Register tail: k in [p*64, p*64+KRH), packed (k,k+1) f32x2, per gate c.
__device__ __forceinline__ void load_tail(u64 wrp[4][KRH / 2],
                                          const float* __restrict__ W,
                                          int p, int q) {
#pragma unroll
    for (int c = 0; c < 4; c++) {
        const int col = c * 128 + q;
#pragma unroll
        for (int j = 0; j < KRH / 2; j++) {
            F2U v;
            int k = p * 64 + 2 * j;
            v.f.x = __ldg(W + (size_t)k * NG + col);
            v.f.y = __ldg(W + (size_t)(k + 1) * NG + col);
            wrp[c][j] = v.u;
        }
    }
}

// Partial gate GEMV over this thread's k-half. g[c][m] out.
__device__ __forceinline__ void gate_gemv_half(
    const float* __restrict__ hsR,
    const float* __restrict__ Wsm,
    const u64 wrp[4][KRH / 2],
    int p, int q,
    const float bb[4], const float wih[4],
    float x0, float x1, float x2, float x3, int isP0,
    float g[4][4])
{
    u64 acc[4][4];
    F2U t;
    if (isP0) {
        float xv[4] = {x0, x1, x2, x3};
#pragma unroll
        for (int c = 0; c < 4; c++)
#pragma unroll
            for (int m = 0; m < 4; m++) {
                t.f = make_float2(fmaf(xv[m], wih[c], bb[c]), 0.f);
                acc[c][m] = t.u;
            }
    } else {
#pragma unroll
        for (int c = 0; c < 4; c++)
#pragma unroll
            for (int m = 0; m < 4; m++) acc[c][m] = 0ull;
    }

    const int kb = p * 64;
    const ulonglong2* hp0 = reinterpret_cast<const ulonglong2*>(hsR + 0 * H_ + kb);
    const ulonglong2* hp1 = reinterpret_cast<const ulonglong2*>(hsR + 1 * H_ + kb);
    const ulonglong2* hp2 = reinterpret_cast<const ulonglong2*>(hsR + 2 * H_ + kb);
    const ulonglong2* hp3 = reinterpret_cast<const ulonglong2*>(hsR + 3 * H_ + kb);

    // register-weight part: k-offsets [0, KRH)
#pragma unroll
    for (int i = 0; i < KRH / 4; i++) {
        ulonglong2 h0 = hp0[i], h1 = hp1[i], h2 = hp2[i], h3 = hp3[i];
#pragma unroll
        for (int c = 0; c < 4; c++) {
            u64 wa = wrp[c][2 * i], wb = wrp[c][2 * i + 1];
            fma2(acc[c][0], h0.x, wa); fma2(acc[c][0], h0.y, wb);
            fma2(acc[c][1], h1.x, wa); fma2(acc[c][1], h1.y, wb);
            fma2(acc[c][2], h2.x, wa); fma2(acc[c][2], h2.y, wb);
            fma2(acc[c][3], h3.x, wa); fma2(acc[c][3], h3.y, wb);
        }
    }
    // smem-weight part: k-offsets [KRH, 64)
    const float* w0 = Wsm + wslot(0, p, q) * WSTR;
    const float* w1 = Wsm + wslot(1, p, q) * WSTR;
    const float* w2 = Wsm + wslot(2, p, q) * WSTR;
    const float* w3 = Wsm + wslot(3, p, q) * WSTR;
#pragma unroll
    for (int i = 0; i < KSH / 4; i++) {
        ulonglong2 wv0 = *reinterpret_cast<const ulonglong2*>(w0 + 4 * i);
        ulonglong2 wv1 = *reinterpret_cast<const ulonglong2*>(w1 + 4 * i);
        ulonglong2 wv2 = *reinterpret_cast<const ulonglong2*>(w2 + 4 * i);
        ulonglong2 wv3 = *reinterpret_cast<const ulonglong2*>(w3 + 4 * i);
        const int ib = KRH / 4 + i;
        ulonglong2 h0 = hp0[ib], h1 = hp1[ib], h2 = hp2[ib], h3 = hp3[ib];
        fma2(acc[0][0], h0.x, wv0.x); fma2(acc[0][0], h0.y, wv0.y);
        fma2(acc[0][1], h1.x, wv0.x); fma2(acc[0][1], h1.y, wv0.y);
        fma2(acc[0][2], h2.x, wv0.x); fma2(acc[0][2], h2.y, wv0.y);
        fma2(acc[0][3], h3.x, wv0.x); fma2(acc[0][3], h3.y, wv0.y);
        fma2(acc[1][0], h0.x, wv1.x); fma2(acc[1][0], h0.y, wv1.y);
        fma2(acc[1][1], h1.x, wv1.x); fma2(acc[1][1], h1.y, wv1.y);
        fma2(acc[1][2], h2.x, wv1.x); fma2(acc[1][2], h2.y, wv1.y);
        fma2(acc[1][3], h3.x, wv1.x); fma2(acc[1][3], h3.y, wv1.y);
        fma2(acc[2][0], h0.x, wv2.x); fma2(acc[2][0], h0.y, wv2.y);
        fma2(acc[2][1], h1.x, wv2.x); fma2(acc[2][1], h1.y, wv2.y);
        fma2(acc[2][2], h2.x, wv2.x); fma2(acc[2][2], h2.y, wv2.y);
        fma2(acc[2][3], h3.x, wv2.x); fma2(acc[2][3], h3.y, wv2.y);
        fma2(acc[3][0], h0.x, wv3.x); fma2(acc[3][0], h0.y, wv3.y);
        fma2(acc[3][1], h1.x, wv3.x); fma2(acc[3][1], h1.y, wv3.y);
        fma2(acc[3][2], h2.x, wv3.x); fma2(acc[3][2], h2.y, wv3.y);
        fma2(acc[3][3], h3.x, wv3.x); fma2(acc[3][3], h3.y, wv3.y);
    }
#pragma unroll
    for (int c = 0; c < 4; c++)
#pragma unroll
        for (int m = 0; m < 4; m++) {
            t.u = acc[c][m];
            g[c][m] = t.f.x + t.f.y;
        }
}

__global__ __launch_bounds__(TPB, 1)
void seq2seq_kernel(
    const float* __restrict__ inputs,
    const float* __restrict__ Wih_e, const float* __restrict__ Whh_e, const float* __restrict__ b_e,
    const float* __restrict__ Wih_d, const float* __restrict__ Whh_d, const float* __restrict__ b_d,
    const float* __restrict__ We,    const float* __restrict__ Wd,
    const float* __restrict__ Wv,    const float* __restrict__ Wf,    const float* __restrict__ bf,
    float* __restrict__ out, int write_attn)
{
    extern __shared__ float smf[];
    float* Wsm     = smf;                      // 1024*WSTR = 45056
    float* hsA     = Wsm + 1024 * WSTR;        // 512
    float* hsB     = hsA + R_ * H_;            // 512
    float* ctx     = hsB + R_ * H_;            // 512
    float* pbuf    = ctx + R_ * H_;            // 2*128*PSTR = 3072
    float* xs      = pbuf + 2 * 128 * PSTR;    // 4
    float* xenc    = xs + R_;                  // 56
    float* attn    = xenc + R_ * S_;           // 56
    float* attnAcc = attn + R_ * S_;           // 56
    float* red     = attnAcc + R_ * S_;        // 224
    // total 50048 floats = 200192 B

    const int tid  = threadIdx.x;
    const int lane = tid & 31;
    const int wg   = (tid >> 5) & 3;
    const int cta  = blockIdx.x;
    const int p    = tid >> 7;     // k-half
    const int q    = tid & 127;    // unit
    const int isP0 = (p == 0);
    const int m0   = 2 * p;        // this thread finalizes rows m0, m0+1
    const int ob   = 2 - 2 * p;    // rows it ships to partner

    u64 wrp[4][KRH / 2];
    float bb[4], wih[4];

    // ---- init + stage encoder weights ----
    stage_w(Wsm, Whh_e, tid);
    load_tail(wrp, Whh_e, p, q);
    if (tid < R_ * S_) {
        attnAcc[tid] = 0.f;
        int mm = tid / S_, tt = tid - mm * S_;
        xenc[tid] = inputs[(cta * R_ + mm) * S_ + tt];
    }
    if (tid < R_) xs[tid] = inputs[(cta * R_ + tid) * S_ + (S_ - 1)];
    for (int idx = tid; idx < R_ * H_; idx += TPB) hsA[idx] = 0.f;

    float creg[2] = {0.f, 0.f};
    float* hsR = hsA;
    float* hsW = hsB;

#pragma unroll
    for (int c = 0; c < 4; c++) {
        bb[c]  = b_e[c * 128 + q];
        wih[c] = Wih_e[c * 128 + q];
    }
    const float wv_j = Wv[q];
    const float wf_j = Wf[q];
    const float bf0  = bf[0];
    __syncthreads();

    float* pw = pbuf + p * (128 * PSTR) + q * PSTR;
    const float* pr = pbuf + (1 - p) * (128 * PSTR) + q * PSTR;

    // ================= Encoder: 14 steps =================
    for (int t = 0; t < S_; t++) {
        float x0 = 0.f, x1 = 0.f, x2 = 0.f, x3 = 0.f;
        if (isP0) {
            x0 = xenc[0 * S_ + t]; x1 = xenc[1 * S_ + t];
            x2 = xenc[2 * S_ + t]; x3 = xenc[3 * S_ + t];
        }
        float g[4][4];
        gate_gemv_half(hsR, Wsm, wrp, p, q, bb, wih, x0, x1, x2, x3, isP0, g);
        // ship partner's rows
        float4 s0 = make_float4(g[0][ob], g[0][ob + 1], g[1][ob], g[1][ob + 1]);
        float4 s1 = make_float4(g[2][ob], g[2][ob + 1], g[3][ob], g[3][ob + 1]);
        *reinterpret_cast<float4*>(pw)     = s0;
        *reinterpret_cast<float4*>(pw + 4) = s1;
        __syncthreads();
        float4 r0 = *reinterpret_cast<const float4*>(pr);
        float4 r1 = *reinterpret_cast<const float4*>(pr + 4);
        float rp[8] = {r0.x, r0.y, r0.z, r0.w, r1.x, r1.y, r1.z, r1.w};
#pragma unroll
        for (int mi = 0; mi < 2; mi++) {
            int m = m0 + mi;
            float gi = g[0][m] + rp[0 + mi];
            float gf = g[1][m] + rp[2 + mi];
            float gg = g[2][m] + rp[4 + mi];
            float go = g[3][m] + rp[6 + mi];
            float c = sigm(gf) * creg[mi] + sigm(gi) * tanh_(gg);
            creg[mi] = c;
            float h = sigm(go) * tanh_(c);
            hsW[m * H_ + q] = h;
            g_enc[((size_t)(cta * R_ + m)) * S_ * H_ + t * H_ + q] = h;
        }
        __syncthreads();
        float* tmp = hsR; hsR = hsW; hsW = tmp;
    }

    // ---- restage for decoder ----
    stage_w(Wsm, Whh_d, tid);
    load_tail(wrp, Whh_d, p, q);
#pragma unroll
    for (int c = 0; c < 4; c++) {
        bb[c]  = b_d[c * 128 + q];
        wih[c] = Wih_d[c * 128 + q];
    }

    // ---- encProj[t][j] = sum_k enc[t][k] * We[k][j] (once; reused 8x) ----
    for (int cell = tid; cell < R_ * H_; cell += TPB) {
        int m = cell >> 7, jj = cell & 127;
        const float* eb = g_enc + ((size_t)(cta * R_ + m)) * S_ * H_;
        float acc[S_];
#pragma unroll
        for (int t = 0; t < S_; t++) acc[t] = 0.f;
#pragma unroll 4
        for (int k = 0; k < H_; k++) {
            float we = __ldg(We + k * H_ + jj);
#pragma unroll
            for (int t = 0; t < S_; t++) acc[t] += __ldg(eb + t * H_ + k) * we;
        }
        float* pb = g_encProj + ((size_t)(cta * R_ + m)) * S_ * H_;
#pragma unroll
        for (int t = 0; t < S_; t++) pb[t * H_ + jj] = acc[t];
    }
    __syncthreads();

    // ================= Decoder: 8 steps =================
    for (int s = 0; s < TLEN; s++) {
        // hWd[m][j] = h[m] @ Wd
        for (int cell = tid; cell < R_ * H_; cell += TPB) {
            int m = cell >> 7, jj = cell & 127;
            float acc = 0.f;
#pragma unroll 8
            for (int k = 0; k < H_; k++)
                acc += hsR[m * H_ + k] * __ldg(Wd + k * H_ + jj);
            ctx[cell] = acc;
        }
        __syncthreads();

        // scores[m][t] = sum_j tanh(encProj + hWd) * Wv
#pragma unroll
        for (int pass = 0; pass < 2; pass++) {
            int m = p + 2 * pass;
            float hwd = ctx[m * H_ + q];
            const float* ep = g_encProj + ((size_t)(cta * R_ + m)) * S_ * H_;
#pragma unroll
            for (int t = 0; t < S_; t++) {
                float v = tanh_(ep[t * H_ + q] + hwd) * wv_j;
                v = warpsum(v);
                if (lane == 0) red[(m * S_ + t) * 4 + wg] = v;
            }
        }
        __syncthreads();
        if (tid < R_ * S_) {
            int b4 = tid * 4;
            attn[tid] = red[b4] + red[b4 + 1] + red[b4 + 2] + red[b4 + 3];
        }
        __syncthreads();
        if (tid < R_) {
            float mx = attn[tid * S_];
#pragma unroll
            for (int t = 1; t < S_; t++) mx = fmaxf(mx, attn[tid * S_ + t]);
            float ssum = 0.f, ex[S_];
#pragma unroll
            for (int t = 0; t < S_; t++) { ex[t] = __expf(attn[tid * S_ + t] - mx); ssum += ex[t]; }
            float inv = __fdividef(1.f, ssum);
#pragma unroll
            for (int t = 0; t < S_; t++) {
                float a_ = ex[t] * inv;
                attn[tid * S_ + t] = a_;
                attnAcc[tid * S_ + t] += a_;
            }
        }
        __syncthreads();
        // context[m][j] = sum_t attn * enc
        for (int cell = tid; cell < R_ * H_; cell += TPB) {
            int m = cell >> 7, jj = cell & 127;
            const float* eb = g_enc + ((size_t)(cta * R_ + m)) * S_ * H_;
            float acc = 0.f;
#pragma unroll
            for (int t = 0; t < S_; t++) acc += attn[m * S_ + t] * __ldg(eb + t * H_ + jj);
            ctx[cell] = acc;
        }
        __syncthreads();

        // inner decoder LSTM: 129 scalar-input steps
        for (int js = 0; js < H_ + 1; js++) {
            float x0 = 0.f, x1 = 0.f, x2 = 0.f, x3 = 0.f;
            if (isP0) {
                if (js < H_) {
                    x0 = ctx[js]; x1 = ctx[H_ + js];
                    x2 = ctx[2 * H_ + js]; x3 = ctx[3 * H_ + js];
                } else {
                    x0 = xs[0]; x1 = xs[1]; x2 = xs[2]; x3 = xs[3];
                }
            }
            float g[4][4];
            gate_gemv_half(hsR, Wsm, wrp, p, q, bb, wih, x0, x1, x2, x3, isP0, g);
            float4 s0 = make_float4(g[0][ob], g[0][ob + 1], g[1][ob], g[1][ob + 1]);
            float4 s1 = make_float4(g[2][ob], g[2][ob + 1], g[3][ob], g[3][ob + 1]);
            *reinterpret_cast<float4*>(pw)     = s0;
            *reinterpret_cast<float4*>(pw + 4) = s1;
            __syncthreads();
            float4 r0 = *reinterpret_cast<const float4*>(pr);
            float4 r1 = *reinterpret_cast<const float4*>(pr + 4);
            float rp[8] = {r0.x, r0.y, r0.z, r0.w, r1.x, r1.y, r1.z, r1.w};
#pragma unroll
            for (int mi = 0; mi < 2; mi++) {
                int m = m0 + mi;
                float gi = g[0][m] + rp[0 + mi];
                float gf = g[1][m] + rp[2 + mi];
                float gg = g[2][m] + rp[4 + mi];
                float go = g[3][m] + rp[6 + mi];
                float c = sigm(gf) * creg[mi] + sigm(gi) * tanh_(gg);
                creg[mi] = c;
                hsW[m * H_ + q] = sigm(go) * tanh_(c);
            }
            __syncthreads();
            float* tmp = hsR; hsR = hsW; hsW = tmp;
        }

        // out = h @ Wf + bf ; feed back as next x
#pragma unroll
        for (int pass = 0; pass < 2; pass++) {
            int m = p + 2 * pass;
            float v = hsR[m * H_ + q] * wf_j;
            v = warpsum(v);
            if (lane == 0) red[m * 4 + wg] = v;
        }
        __syncthreads();
        if (tid < R_) {
            float o = red[tid * 4] + red[tid * 4 + 1] + red[tid * 4 + 2] + red[tid * 4 + 3] + bf0;
            out[(cta * R_ + tid) * TLEN + s] = o;
            xs[tid] = o;
        }
        __syncthreads();
    }

    if (write_attn) {
        for (int idx = tid; idx < R_ * S_; idx += TPB)
            out[B_ * TLEN + (cta * R_ + idx / S_) * S_ + (idx % S_)] = attnAcc[idx];
    }
}

extern "C" void kernel_launch(void* const* d_in, const int* in_sizes, int n_in,
                              void* d_out, int out_size) {
    const float* inputs = (const float*)d_in[0];
    const int off = (n_in >= 13 && in_sizes[1] == 1) ? 2 : 1;
    const float* Wih_e = (const float*)d_in[off + 0];
    const float* Whh_e = (const float*)d_in[off + 1];
    const float* b_e   = (const float*)d_in[off + 2];
    const float* Wih_d = (const float*)d_in[off + 3];
    const float* Whh_d = (const float*)d_in[off + 4];
    const float* b_d   = (const float*)d_in[off + 5];
    const float* We    = (const float*)d_in[off + 6];
    const float* Wd    = (const float*)d_in[off + 7];
    const float* Wv    = (const float*)d_in[off + 8];
    const float* Wf    = (const float*)d_in[off + 9];
    const float* bf    = (const float*)d_in[off + 10];

    const int smem_floats = 1024 * WSTR + 3 * R_ * H_ + 2 * 128 * PSTR
                          + R_ + 3 * R_ * S_ + R_ * S_ * 4;
    const int smem_bytes = smem_floats * (int)sizeof(float);  // 200192

    cudaFuncSetAttribute(seq2seq_kernel,
                         cudaFuncAttributeMaxDynamicSharedMemorySize, smem_bytes);

    const int write_attn = (out_size >= B_ * TLEN + B_ * S_) ? 1 : 0;

    seq2seq_kernel<<<NCTA, TPB, smem_bytes>>>(
        inputs, Wih_e, Whh_e, b_e, Wih_d, Whh_d, b_d,
        We, Wd, Wv, Wf, bf, (float*)d_out, write_attn);
}